// round 8
// baseline (speedup 1.0000x reference)
#include <cuda_runtime.h>
#include <cuda_bf16.h>
#include <cstdint>

// bf16 HMMA (legacy mma.sync — available on plain compute_103 PTX, unlike tcgen05)
#define MMA(c, a, b0, b1) \
    asm volatile("mma.sync.aligned.m16n8k16.row.col.f32.bf16.bf16.f32 " \
        "{%0,%1,%2,%3}, {%4,%5,%6,%7}, {%8,%9}, {%0,%1,%2,%3};" \
        : "+f"((c)[0]), "+f"((c)[1]), "+f"((c)[2]), "+f"((c)[3]) \
        : "r"((a)[0]), "r"((a)[1]), "r"((a)[2]), "r"((a)[3]), "r"(b0), "r"(b1))

__device__ __forceinline__ uint32_t pack_bf2(__nv_bfloat16 a, __nv_bfloat16 b) {
    __nv_bfloat162 t(a, b);                  // .x = a (low half)
    return *reinterpret_cast<uint32_t*>(&t);
}

// Shapes: B=64, C=256, H=W=56, WS=7, HEADS=16, DH=16; 49 tokens/window (pad 64).
constexpr int AST = 264;                     // bf16 row stride: 528 B; 528%128=16 -> 1-wf fragment loads
constexpr int A_SZ = 64 * AST * 2;           // 33792 B
constexpr int B_SZ = 96 * AST * 2;           // 50688 B
constexpr int OFF_AH = 0;
constexpr int OFF_AL = OFF_AH + A_SZ;
constexpr int OFF_BH = OFF_AL + A_SZ;        // 67584
constexpr int OFF_BL = OFF_BH + B_SZ;        // 118272
constexpr int OFF_QT = OFF_BL + B_SZ;        // 168960: qt[96][57] f32
constexpr int OFF_ST = OFF_QT + 96 * 57 * 4; // 190848: st[2][49][50] f32
constexpr int SMEM_TOTAL = OFF_ST + 2 * 49 * 50 * 4;   // 210448 B

__global__ __launch_bounds__(256, 1)
void wsa_kernel(const float* __restrict__ x,
                const float* __restrict__ bng, const float* __restrict__ bnb,
                const float* __restrict__ bnm, const float* __restrict__ bnv,
                const float* __restrict__ qkw, const float* __restrict__ vw,
                float* __restrict__ out) {
    extern __shared__ char smem[];
    __nv_bfloat16* Ah = (__nv_bfloat16*)(smem + OFF_AH);
    __nv_bfloat16* Al = (__nv_bfloat16*)(smem + OFF_AL);
    __nv_bfloat16* Bh = (__nv_bfloat16*)(smem + OFF_BH);
    __nv_bfloat16* Bl = (__nv_bfloat16*)(smem + OFF_BL);
    float* qt = (float*)(smem + OFF_QT);     // [oc][t] stride 57
    float* st = (float*)(smem + OFF_ST);     // [ah][j][i] stride 50

    const int tid  = threadIdx.x;
    const int lane = tid & 31;
    const int warp = tid >> 5;
    const int wb   = blockIdx.x;
    const int b    = wb >> 6;
    const int n1   = (wb >> 3) & 7;
    const int n2   = wb & 7;

    // ---- BN + stage A (tokens) as bf16 hi/lo, row-major [t][k], k = channel = tid ----
    {
        const float inv = bng[tid] / sqrtf(bnv[tid] + 1e-6f);
        const float shf = bnb[tid] - bnm[tid] * inv;
        const float* xb = x + ((size_t)b * 256 + tid) * 3136 + n1 * 56 + n2;
        #pragma unroll 7
        for (int t = 0; t < 49; ++t) {
            const int ti = t / 7, tj = t - (t / 7) * 7;
            const float v = fmaf(xb[ti * 448 + tj * 8], inv, shf);
            const __nv_bfloat16 h = __float2bfloat16(v);
            Ah[t * AST + tid] = h;
            Al[t * AST + tid] = __float2bfloat16(v - __bfloat162float(h));
        }
        for (int i = tid; i < 15 * 128; i += 256) {        // zero pad rows 49..63
            const int row = 49 + (i >> 7), c = (i & 127) * 2;
            *(uint32_t*)&Ah[row * AST + c] = 0u;
            *(uint32_t*)&Al[row * AST + c] = 0u;
        }
    }

    const int mh = warp >> 2, nq = warp & 3;   // warp tile: 32m x 24n
    const int m0 = mh * 32, n0 = nq * 24;
    float* outb = out + (size_t)b * 256 * 3136 + n1 * 56 + n2;

    for (int hp = 0; hp < 8; ++hp) {           // head pair: heads 2hp, 2hp+1
        // ---- stage head-pair weights: fp32 -> bf16 hi/lo, [oc96][k256] ----
        #pragma unroll 4
        for (int ii = 0; ii < 24; ++ii) {
            const int idx = tid + ii * 256;    // 96 rows x 64 float4
            const int r = idx >> 6, f4 = idx & 63;
            const int hh = (r >= 48) ? 1 : 0;
            const int oc = r - 48 * hh;
            const int head = hp * 2 + hh;
            const float* src = (oc < 16) ? qkw + (head * 16 + oc) * 256
                             : (oc < 32) ? qkw + (256 + head * 16 + (oc - 16)) * 256
                                         : vw + (head * 16 + (oc - 32)) * 256;
            const float4 wv = *(const float4*)(src + f4 * 4);
            const __nv_bfloat16 hx = __float2bfloat16(wv.x), hy = __float2bfloat16(wv.y);
            const __nv_bfloat16 hz = __float2bfloat16(wv.z), hw = __float2bfloat16(wv.w);
            *(uint2*)&Bh[r * AST + f4 * 4] = make_uint2(pack_bf2(hx, hy), pack_bf2(hz, hw));
            *(uint2*)&Bl[r * AST + f4 * 4] = make_uint2(
                pack_bf2(__float2bfloat16(wv.x - __bfloat162float(hx)),
                         __float2bfloat16(wv.y - __bfloat162float(hy))),
                pack_bf2(__float2bfloat16(wv.z - __bfloat162float(hz)),
                         __float2bfloat16(wv.w - __bfloat162float(hw))));
        }
        __syncthreads();

        // ---- projection: M64 x N96 x K256, split-bf16 (Ah*Bh + Ah*Bl + Al*Bh) ----
        float acc[2][3][4];
        #pragma unroll
        for (int mt = 0; mt < 2; ++mt)
            #pragma unroll
            for (int nt = 0; nt < 3; ++nt)
                #pragma unroll
                for (int e = 0; e < 4; ++e) acc[mt][nt][e] = 0.f;

        const int arow = lane >> 2;
        #pragma unroll 2
        for (int ks = 0; ks < 16; ++ks) {
            const int kk = ks * 16 + 2 * (lane & 3);
            uint32_t ah[2][4], al[2][4];
            #pragma unroll
            for (int mt = 0; mt < 2; ++mt) {
                const int r0 = (m0 + mt * 16 + arow) * AST;
                ah[mt][0] = *(const uint32_t*)&Ah[r0 + kk];
                ah[mt][1] = *(const uint32_t*)&Ah[r0 + 8 * AST + kk];
                ah[mt][2] = *(const uint32_t*)&Ah[r0 + kk + 8];
                ah[mt][3] = *(const uint32_t*)&Ah[r0 + 8 * AST + kk + 8];
                al[mt][0] = *(const uint32_t*)&Al[r0 + kk];
                al[mt][1] = *(const uint32_t*)&Al[r0 + 8 * AST + kk];
                al[mt][2] = *(const uint32_t*)&Al[r0 + kk + 8];
                al[mt][3] = *(const uint32_t*)&Al[r0 + 8 * AST + kk + 8];
            }
            #pragma unroll
            for (int nt = 0; nt < 3; ++nt) {
                const int nr = (n0 + nt * 8 + arow) * AST;
                const uint32_t bh0 = *(const uint32_t*)&Bh[nr + kk];
                const uint32_t bh1 = *(const uint32_t*)&Bh[nr + kk + 8];
                const uint32_t bl0 = *(const uint32_t*)&Bl[nr + kk];
                const uint32_t bl1 = *(const uint32_t*)&Bl[nr + kk + 8];
                MMA(acc[0][nt], ah[0], bh0, bh1);
                MMA(acc[1][nt], ah[1], bh0, bh1);
                MMA(acc[0][nt], ah[0], bl0, bl1);
                MMA(acc[1][nt], ah[1], bl0, bl1);
                MMA(acc[0][nt], al[0], bh0, bh1);
                MMA(acc[1][nt], al[1], bh0, bh1);
            }
        }

        // ---- epilogue: acc -> qt[oc][t] (transpose), ReLU on v cols, guard pad rows ----
        #pragma unroll
        for (int mt = 0; mt < 2; ++mt)
            #pragma unroll
            for (int nt = 0; nt < 3; ++nt) {
                const int row0 = m0 + mt * 16 + arow, row1 = row0 + 8;
                const int col  = n0 + nt * 8 + 2 * (lane & 3);
                const bool relu = ((col % 48) >= 32);
                float c0 = acc[mt][nt][0], c1 = acc[mt][nt][1];
                float c2 = acc[mt][nt][2], c3 = acc[mt][nt][3];
                if (relu) {
                    c0 = fmaxf(c0, 0.f); c1 = fmaxf(c1, 0.f);
                    c2 = fmaxf(c2, 0.f); c3 = fmaxf(c3, 0.f);
                }
                if (row0 < 49) { qt[col * 57 + row0] = c0; qt[(col + 1) * 57 + row0] = c1; }
                if (row1 < 49) { qt[col * 57 + row1] = c2; qt[(col + 1) * 57 + row1] = c3; }
            }
        __syncthreads();

        // ---- S = (q @ k^T) * 0.25, both heads in parallel ----
        {
            const int ah2 = warp >> 2, wq2 = warp & 3;
            const float* qb = qt + (ah2 * 48) * 57;
            const bool act1 = (lane + 32) < 49;
            float q0[16], q1[16];
            #pragma unroll
            for (int dd = 0; dd < 16; ++dd) {
                q0[dd] = qb[dd * 57 + lane];
                q1[dd] = act1 ? qb[dd * 57 + lane + 32] : 0.f;
            }
            #pragma unroll 1
            for (int jj = 0; jj < 13; ++jj) {
                const int j = wq2 * 13 + jj;
                if (j < 49) {
                    float s0 = 0.f, s1 = 0.f;
                    #pragma unroll
                    for (int dd = 0; dd < 16; ++dd) {
                        const float kv = qb[(16 + dd) * 57 + j];   // warp-uniform broadcast
                        s0 = fmaf(kv, q0[dd], s0);
                        s1 = fmaf(kv, q1[dd], s1);
                    }
                    st[(ah2 * 49 + j) * 50 + lane] = s0 * 0.25f;
                    if (act1) st[(ah2 * 49 + j) * 50 + lane + 32] = s1 * 0.25f;
                }
            }
        }
        __syncthreads();

        // ---- softmax over j per query i ----
        if (tid < 98) {
            const int ah2 = tid >= 49;
            const int i   = tid - ah2 * 49;
            float* col = st + ah2 * 49 * 50 + i;
            float m = -1e30f;
            #pragma unroll 7
            for (int j = 0; j < 49; ++j) m = fmaxf(m, col[j * 50]);
            float sum = 0.f;
            #pragma unroll 7
            for (int j = 0; j < 49; ++j) {
                const float e = __expf(col[j * 50] - m);
                col[j * 50] = e;
                sum += e;
            }
            const float rs = 1.f / sum;
            #pragma unroll 7
            for (int j = 0; j < 49; ++j) col[j * 50] *= rs;
        }
        __syncthreads();

        // ---- O = P @ V -> scatter to (B, C, H, W) ----
        {
            const int ah2 = warp >> 2;
            const float* vb0 = qt + (ah2 * 48 + 32) * 57;
            const int head = hp * 2 + ah2;
            const bool act1 = (lane + 32) < 49;
            #pragma unroll
            for (int dd = 0; dd < 4; ++dd) {
                const int d = (warp & 3) * 4 + dd;
                const float* vb = vb0 + d * 57;
                float o0 = 0.f, o1 = 0.f;
                #pragma unroll 7
                for (int j = 0; j < 49; ++j) {
                    const float vv = vb[j];                         // warp-uniform broadcast
                    o0 = fmaf(vv, st[(ah2 * 49 + j) * 50 + lane], o0);
                    o1 = fmaf(vv, act1 ? st[(ah2 * 49 + j) * 50 + lane + 32] : 0.f, o1);
                }
                const size_t ch = (size_t)(head * 16 + d) * 3136;
                { const int i = lane, ti = i / 7, tj = i - (i / 7) * 7;
                  outb[ch + ti * 448 + tj * 8] = o0; }
                if (act1) {
                    const int i = lane + 32, ti = i / 7, tj = i - (i / 7) * 7;
                    outb[ch + ti * 448 + tj * 8] = o1;
                }
            }
        }
        __syncthreads();   // st/qt/B reuse ordering for next head pair
    }
}

extern "C" void kernel_launch(void* const* d_in, const int* in_sizes, int n_in,
                              void* d_out, int out_size) {
    const float* x   = (const float*)d_in[0];
    const float* g   = (const float*)d_in[1];
    const float* be  = (const float*)d_in[2];
    const float* mu  = (const float*)d_in[3];
    const float* var = (const float*)d_in[4];
    const float* qkw = (const float*)d_in[5];
    const float* vw  = (const float*)d_in[6];
    float* out = (float*)d_out;

    cudaFuncSetAttribute(wsa_kernel, cudaFuncAttributeMaxDynamicSharedMemorySize, SMEM_TOTAL);
    wsa_kernel<<<4096, 256, SMEM_TOTAL>>>(x, g, be, mu, var, qkw, vw, out);
}

// round 9
// speedup vs baseline: 1.2011x; 1.2011x over previous
#include <cuda_runtime.h>
#include <cuda_bf16.h>
#include <cstdint>

// bf16 HMMA (legacy mma.sync — available on plain compute_103 PTX, unlike tcgen05)
#define MMA(c, a, b0, b1) \
    asm volatile("mma.sync.aligned.m16n8k16.row.col.f32.bf16.bf16.f32 " \
        "{%0,%1,%2,%3}, {%4,%5,%6,%7}, {%8,%9}, {%0,%1,%2,%3};" \
        : "+f"((c)[0]), "+f"((c)[1]), "+f"((c)[2]), "+f"((c)[3]) \
        : "r"((a)[0]), "r"((a)[1]), "r"((a)[2]), "r"((a)[3]), "r"(b0), "r"(b1))

__device__ __forceinline__ uint32_t pack_bf2(__nv_bfloat16 a, __nv_bfloat16 b) {
    __nv_bfloat162 t(a, b);                  // .x = a (low half)
    return *reinterpret_cast<uint32_t*>(&t);
}

// Shapes: B=64, C=256, H=W=56, WS=7, HEADS=16, DH=16; 49 tokens/window (pad 64).
constexpr int AST = 264;                     // bf16 row stride: 528 B; 528%128=16 -> 1-wf fragment loads
constexpr int A_SZ = 64 * AST * 2;           // 33792 B
constexpr int B_SZ = 96 * AST * 2;           // 50688 B
constexpr int OFF_AH = 0;
constexpr int OFF_AL = OFF_AH + A_SZ;
constexpr int OFF_BH = OFF_AL + A_SZ;        // 67584
constexpr int OFF_BL = OFF_BH + B_SZ;        // 118272
constexpr int OFF_QT = OFF_BL + B_SZ;        // 168960: qt[96][57] f32
constexpr int OFF_ST = OFF_QT + 96 * 57 * 4; // 190848: st[2][49][50] f32
constexpr int SMEM_TOTAL = OFF_ST + 2 * 49 * 50 * 4;   // 210448 B

__global__ __launch_bounds__(512, 1)
void wsa_kernel(const float* __restrict__ x,
                const float* __restrict__ bng, const float* __restrict__ bnb,
                const float* __restrict__ bnm, const float* __restrict__ bnv,
                const float* __restrict__ qkw, const float* __restrict__ vw,
                float* __restrict__ out) {
    extern __shared__ char smem[];
    __nv_bfloat16* Ah = (__nv_bfloat16*)(smem + OFF_AH);
    __nv_bfloat16* Al = (__nv_bfloat16*)(smem + OFF_AL);
    __nv_bfloat16* Bh = (__nv_bfloat16*)(smem + OFF_BH);
    __nv_bfloat16* Bl = (__nv_bfloat16*)(smem + OFF_BL);
    float* qt = (float*)(smem + OFF_QT);     // [oc][t] stride 57
    float* st = (float*)(smem + OFF_ST);     // [ah][j][i] stride 50

    const int tid  = threadIdx.x;
    const int lane = tid & 31;
    const int warp = tid >> 5;
    const int wb   = blockIdx.x;
    const int b    = wb >> 6;
    const int n1   = (wb >> 3) & 7;
    const int n2   = wb & 7;

    // ---- BN + stage A (tokens) as bf16 hi/lo, row-major [t][k]; 2 thread-halves split t ----
    {
        const int c  = tid & 255;
        const int th = tid >> 8;             // 0: t 0..24, 1: t 25..48
        const float inv = bng[c] / sqrtf(bnv[c] + 1e-6f);
        const float shf = bnb[c] - bnm[c] * inv;
        const float* xb = x + ((size_t)b * 256 + c) * 3136 + n1 * 56 + n2;
        const int tbeg = th ? 25 : 0, tend = th ? 49 : 25;
        for (int t = tbeg; t < tend; ++t) {
            const int ti = t / 7, tj = t - (t / 7) * 7;
            const float v = fmaf(xb[ti * 448 + tj * 8], inv, shf);
            const __nv_bfloat16 h = __float2bfloat16(v);
            Ah[t * AST + c] = h;
            Al[t * AST + c] = __float2bfloat16(v - __bfloat162float(h));
        }
        for (int i = tid; i < 15 * 128; i += 512) {        // zero pad rows 49..63
            const int row = 49 + (i >> 7), cc = (i & 127) * 2;
            *(uint32_t*)&Ah[row * AST + cc] = 0u;
            *(uint32_t*)&Al[row * AST + cc] = 0u;
        }
    }

    // 16 warps: m-tile = (warp&3)*16, n-tile = (warp>>2)*24
    const int m0 = (warp & 3) * 16, n0 = (warp >> 2) * 24;
    float* outb = out + (size_t)b * 256 * 3136 + n1 * 56 + n2;

    for (int hp = 0; hp < 8; ++hp) {           // head pair: heads 2hp, 2hp+1
        // ---- stage head-pair weights: fp32 -> bf16 hi/lo, [oc96][k256] ----
        #pragma unroll 4
        for (int ii = 0; ii < 12; ++ii) {
            const int idx = tid + ii * 512;    // 96 rows x 64 float4
            const int r = idx >> 6, f4 = idx & 63;
            const int hh = (r >= 48) ? 1 : 0;
            const int oc = r - 48 * hh;
            const int head = hp * 2 + hh;
            const float* src = (oc < 16) ? qkw + (head * 16 + oc) * 256
                             : (oc < 32) ? qkw + (256 + head * 16 + (oc - 16)) * 256
                                         : vw + (head * 16 + (oc - 32)) * 256;
            const float4 wv = *(const float4*)(src + f4 * 4);
            const __nv_bfloat16 hx = __float2bfloat16(wv.x), hy = __float2bfloat16(wv.y);
            const __nv_bfloat16 hz = __float2bfloat16(wv.z), hw = __float2bfloat16(wv.w);
            *(uint2*)&Bh[r * AST + f4 * 4] = make_uint2(pack_bf2(hx, hy), pack_bf2(hz, hw));
            *(uint2*)&Bl[r * AST + f4 * 4] = make_uint2(
                pack_bf2(__float2bfloat16(wv.x - __bfloat162float(hx)),
                         __float2bfloat16(wv.y - __bfloat162float(hy))),
                pack_bf2(__float2bfloat16(wv.z - __bfloat162float(hz)),
                         __float2bfloat16(wv.w - __bfloat162float(hw))));
        }
        __syncthreads();

        // ---- projection: M64 x N96 x K256, split-bf16 (Ah*Bh + Ah*Bl + Al*Bh) ----
        float acc[3][4];
        #pragma unroll
        for (int nt = 0; nt < 3; ++nt)
            #pragma unroll
            for (int e = 0; e < 4; ++e) acc[nt][e] = 0.f;

        const int arow = lane >> 2;
        #pragma unroll 2
        for (int ks = 0; ks < 16; ++ks) {
            const int kk = ks * 16 + 2 * (lane & 3);
            uint32_t ah[4], al[4];
            {
                const int r0 = (m0 + arow) * AST;
                ah[0] = *(const uint32_t*)&Ah[r0 + kk];
                ah[1] = *(const uint32_t*)&Ah[r0 + 8 * AST + kk];
                ah[2] = *(const uint32_t*)&Ah[r0 + kk + 8];
                ah[3] = *(const uint32_t*)&Ah[r0 + 8 * AST + kk + 8];
                al[0] = *(const uint32_t*)&Al[r0 + kk];
                al[1] = *(const uint32_t*)&Al[r0 + 8 * AST + kk];
                al[2] = *(const uint32_t*)&Al[r0 + kk + 8];
                al[3] = *(const uint32_t*)&Al[r0 + 8 * AST + kk + 8];
            }
            #pragma unroll
            for (int nt = 0; nt < 3; ++nt) {
                const int nr = (n0 + nt * 8 + arow) * AST;
                const uint32_t bh0 = *(const uint32_t*)&Bh[nr + kk];
                const uint32_t bh1 = *(const uint32_t*)&Bh[nr + kk + 8];
                const uint32_t bl0 = *(const uint32_t*)&Bl[nr + kk];
                const uint32_t bl1 = *(const uint32_t*)&Bl[nr + kk + 8];
                MMA(acc[nt], ah, bh0, bh1);
                MMA(acc[nt], ah, bl0, bl1);
                MMA(acc[nt], al, bh0, bh1);
            }
        }

        // ---- epilogue: acc -> qt[oc][t] (transpose), ReLU on v cols, guard pad rows ----
        #pragma unroll
        for (int nt = 0; nt < 3; ++nt) {
            const int row0 = m0 + arow, row1 = row0 + 8;
            const int col  = n0 + nt * 8 + 2 * (lane & 3);
            const bool relu = ((col % 48) >= 32);
            float c0 = acc[nt][0], c1 = acc[nt][1];
            float c2 = acc[nt][2], c3 = acc[nt][3];
            if (relu) {
                c0 = fmaxf(c0, 0.f); c1 = fmaxf(c1, 0.f);
                c2 = fmaxf(c2, 0.f); c3 = fmaxf(c3, 0.f);
            }
            if (row0 < 49) { qt[col * 57 + row0] = c0; qt[(col + 1) * 57 + row0] = c1; }
            if (row1 < 49) { qt[col * 57 + row1] = c2; qt[(col + 1) * 57 + row1] = c3; }
        }
        __syncthreads();

        // ---- S = (q @ k^T) * 0.25, 16 warps: 2 heads x 8 j-groups ----
        {
            const int ah2 = warp >> 3, wq2 = warp & 7;
            const float* qb = qt + (ah2 * 48) * 57;
            const bool act1 = (lane + 32) < 49;
            float q0[16], q1[16];
            #pragma unroll
            for (int dd = 0; dd < 16; ++dd) {
                q0[dd] = qb[dd * 57 + lane];
                q1[dd] = act1 ? qb[dd * 57 + lane + 32] : 0.f;
            }
            #pragma unroll
            for (int jj = 0; jj < 7; ++jj) {
                const int j = wq2 * 7 + jj;
                if (j < 49) {
                    float s0 = 0.f, s1 = 0.f;
                    #pragma unroll
                    for (int dd = 0; dd < 16; ++dd) {
                        const float kv = qb[(16 + dd) * 57 + j];   // warp-uniform broadcast
                        s0 = fmaf(kv, q0[dd], s0);
                        s1 = fmaf(kv, q1[dd], s1);
                    }
                    st[(ah2 * 49 + j) * 50 + lane] = s0 * 0.25f;
                    if (act1) st[(ah2 * 49 + j) * 50 + lane + 32] = s1 * 0.25f;
                }
            }
        }
        __syncthreads();

        // ---- softmax over j per query i ----
        if (tid < 98) {
            const int ah2 = tid >= 49;
            const int i   = tid - ah2 * 49;
            float* col = st + ah2 * 49 * 50 + i;
            float m = -1e30f;
            #pragma unroll 7
            for (int j = 0; j < 49; ++j) m = fmaxf(m, col[j * 50]);
            float sum = 0.f;
            #pragma unroll 7
            for (int j = 0; j < 49; ++j) {
                const float e = __expf(col[j * 50] - m);
                col[j * 50] = e;
                sum += e;
            }
            const float rs = 1.f / sum;
            #pragma unroll 7
            for (int j = 0; j < 49; ++j) col[j * 50] *= rs;
        }
        __syncthreads();

        // ---- O = P @ V -> scatter to (B, C, H, W); 16 warps: 2 heads x 8 d-groups ----
        {
            const int ah2 = warp >> 3;
            const float* vb0 = qt + (ah2 * 48 + 32) * 57;
            const int head = hp * 2 + ah2;
            const bool act1 = (lane + 32) < 49;
            #pragma unroll
            for (int dd = 0; dd < 2; ++dd) {
                const int d = (warp & 7) * 2 + dd;
                const float* vb = vb0 + d * 57;
                float o0 = 0.f, o1 = 0.f;
                #pragma unroll 7
                for (int j = 0; j < 49; ++j) {
                    const float vv = vb[j];                         // warp-uniform broadcast
                    o0 = fmaf(vv, st[(ah2 * 49 + j) * 50 + lane], o0);
                    o1 = fmaf(vv, act1 ? st[(ah2 * 49 + j) * 50 + lane + 32] : 0.f, o1);
                }
                const size_t ch = (size_t)(head * 16 + d) * 3136;
                { const int i = lane, ti = i / 7, tj = i - (i / 7) * 7;
                  outb[ch + ti * 448 + tj * 8] = o0; }
                if (act1) {
                    const int i = lane + 32, ti = i / 7, tj = i - (i / 7) * 7;
                    outb[ch + ti * 448 + tj * 8] = o1;
                }
            }
        }
        __syncthreads();   // st/qt/B reuse ordering for next head pair
    }
}

extern "C" void kernel_launch(void* const* d_in, const int* in_sizes, int n_in,
                              void* d_out, int out_size) {
    const float* x   = (const float*)d_in[0];
    const float* g   = (const float*)d_in[1];
    const float* be  = (const float*)d_in[2];
    const float* mu  = (const float*)d_in[3];
    const float* var = (const float*)d_in[4];
    const float* qkw = (const float*)d_in[5];
    const float* vw  = (const float*)d_in[6];
    float* out = (float*)d_out;

    cudaFuncSetAttribute(wsa_kernel, cudaFuncAttributeMaxDynamicSharedMemorySize, SMEM_TOTAL);
    wsa_kernel<<<4096, 512, SMEM_TOTAL>>>(x, g, be, mu, var, qkw, vw, out);
}

// round 10
// speedup vs baseline: 1.4630x; 1.2181x over previous
#include <cuda_runtime.h>
#include <cuda_bf16.h>
#include <cstdint>

// bf16 HMMA (legacy mma.sync — available on plain compute_103 PTX, unlike tcgen05)
#define MMA(c, a, b0, b1) \
    asm volatile("mma.sync.aligned.m16n8k16.row.col.f32.bf16.bf16.f32 " \
        "{%0,%1,%2,%3}, {%4,%5,%6,%7}, {%8,%9}, {%0,%1,%2,%3};" \
        : "+f"((c)[0]), "+f"((c)[1]), "+f"((c)[2]), "+f"((c)[3]) \
        : "r"((a)[0]), "r"((a)[1]), "r"((a)[2]), "r"((a)[3]), "r"(b0), "r"(b1))

__device__ __forceinline__ void cp16(uint32_t dst, const void* src) {
    asm volatile("cp.async.cg.shared.global [%0], [%1], 16;" :: "r"(dst), "l"(src));
}
__device__ __forceinline__ uint32_t smem_u32(const void* p) {
    uint32_t a;
    asm("{ .reg .u64 t; cvta.to.shared.u64 t, %1; cvt.u32.u64 %0, t; }" : "=r"(a) : "l"(p));
    return a;
}

// Pre-converted weights: [hp][96 rows][256 k] bf16 hi / lo. Row r of head-pair hp:
// hh=r>=48, oc=r-48*hh, head=2hp+hh; oc<16:q, <32:k, else v.
__device__ __nv_bfloat16 gWh[768 * 256];
__device__ __nv_bfloat16 gWl[768 * 256];

__global__ void wconv_kernel(const float* __restrict__ qkw, const float* __restrict__ vw) {
    const int g = blockIdx.x;          // 0..767
    const int k = threadIdx.x;         // 0..255
    const int hp = g / 96, r = g - hp * 96;
    const int hh = (r >= 48) ? 1 : 0;
    const int oc = r - 48 * hh;
    const int head = hp * 2 + hh;
    const float* src = (oc < 16) ? qkw + (head * 16 + oc) * 256
                     : (oc < 32) ? qkw + (256 + head * 16 + (oc - 16)) * 256
                                 : vw + (head * 16 + (oc - 32)) * 256;
    const float v = src[k];
    const __nv_bfloat16 h = __float2bfloat16(v);
    gWh[g * 256 + k] = h;
    gWl[g * 256 + k] = __float2bfloat16(v - __bfloat162float(h));
}

// Shapes: B=64, C=256, H=W=56, WS=7, HEADS=16, DH=16; 49 tokens/window (pad 64).
constexpr int AST = 264;                     // bf16 row stride: 528 B; 528%128=16 -> 1-wf fragment loads
constexpr int A_SZ = 64 * AST * 2;           // 33792 B
constexpr int B_SZ = 96 * AST * 2;           // 50688 B
constexpr int OFF_AH = 0;
constexpr int OFF_AL = OFF_AH + A_SZ;
constexpr int OFF_BH = OFF_AL + A_SZ;        // 67584
constexpr int OFF_BL = OFF_BH + B_SZ;        // 118272
constexpr int OFF_QT = OFF_BL + B_SZ;        // 168960: qt[96][57] f32
constexpr int OFF_ST = OFF_QT + 96 * 57 * 4; // 190848: st[ah][49][50] f32
constexpr int SMEM_TOTAL = OFF_ST + 2 * 49 * 50 * 4;   // 210448 B

// Issue cp.async for head-pair hp's weights (hi+lo), one commit group.
__device__ __forceinline__ void stage_weights(uint32_t sb, int hp, int tid) {
    const __nv_bfloat16* srcH = gWh + hp * 96 * 256;
    const __nv_bfloat16* srcL = gWl + hp * 96 * 256;
    #pragma unroll
    for (int i = 0; i < 6; ++i) {
        const int idx = tid + i * 512;         // 96 rows x 32 chunks of 16 B
        const int r = idx >> 5, c8 = (idx & 31) * 8;
        cp16(sb + OFF_BH + (r * AST + c8) * 2, srcH + r * 256 + c8);
        cp16(sb + OFF_BL + (r * AST + c8) * 2, srcL + r * 256 + c8);
    }
    asm volatile("cp.async.commit_group;" ::: "memory");
}

__global__ __launch_bounds__(512, 1)
void wsa_kernel(const float* __restrict__ x,
                const float* __restrict__ bng, const float* __restrict__ bnb,
                const float* __restrict__ bnm, const float* __restrict__ bnv,
                float* __restrict__ out) {
    extern __shared__ char smem[];
    __nv_bfloat16* Ah = (__nv_bfloat16*)(smem + OFF_AH);
    __nv_bfloat16* Al = (__nv_bfloat16*)(smem + OFF_AL);
    __nv_bfloat16* Bh = (__nv_bfloat16*)(smem + OFF_BH);
    __nv_bfloat16* Bl = (__nv_bfloat16*)(smem + OFF_BL);
    float* qt = (float*)(smem + OFF_QT);     // [oc][t] stride 57 (q pre-scaled by 0.25)
    float* st = (float*)(smem + OFF_ST);     // [ah][j][i] stride 50

    const uint32_t sb = smem_u32(smem);
    const int tid  = threadIdx.x;
    const int lane = tid & 31;
    const int warp = tid >> 5;
    const int wb   = blockIdx.x;
    const int b    = wb >> 6;
    const int n1   = (wb >> 3) & 7;
    const int n2   = wb & 7;

    // Kick off hp=0 weight staging immediately (overlaps the x gather below).
    stage_weights(sb, 0, tid);

    // ---- BN + stage A (tokens) as bf16 hi/lo, row-major [t][k]; 2 thread-halves split t ----
    {
        const int c  = tid & 255;
        const int th = tid >> 8;             // 0: t 0..24, 1: t 25..48
        const float inv = bng[c] / sqrtf(bnv[c] + 1e-6f);
        const float shf = bnb[c] - bnm[c] * inv;
        const float* xb = x + ((size_t)b * 256 + c) * 3136 + n1 * 56 + n2;
        const int tbeg = th ? 25 : 0, tend = th ? 49 : 25;
        for (int t = tbeg; t < tend; ++t) {
            const int ti = t / 7, tj = t - (t / 7) * 7;
            const float v = fmaf(xb[ti * 448 + tj * 8], inv, shf);
            const __nv_bfloat16 h = __float2bfloat16(v);
            Ah[t * AST + c] = h;
            Al[t * AST + c] = __float2bfloat16(v - __bfloat162float(h));
        }
        for (int i = tid; i < 15 * 128; i += 512) {        // zero pad rows 49..63
            const int row = 49 + (i >> 7), cc = (i & 127) * 2;
            *(uint32_t*)&Ah[row * AST + cc] = 0u;
            *(uint32_t*)&Al[row * AST + cc] = 0u;
        }
    }

    // 16 warps: m-tile = (warp&3)*16, n-tile = (warp>>2)*24
    const int m0 = (warp & 3) * 16, n0 = (warp >> 2) * 24;
    float* outb = out + (size_t)b * 256 * 3136 + n1 * 56 + n2;

    for (int hp = 0; hp < 8; ++hp) {           // head pair: heads 2hp, 2hp+1
        // Weights for this hp were issued earlier; drain + publish (also orders A staging
        // on hp=0 and last hp's attention reads of qt/st before this hp overwrites them).
        asm volatile("cp.async.wait_group 0;" ::: "memory");
        __syncthreads();

        // ---- projection: M64 x N96 x K256, split-bf16 (Ah*Bh + Ah*Bl + Al*Bh) ----
        float acc[3][4];
        #pragma unroll
        for (int nt = 0; nt < 3; ++nt)
            #pragma unroll
            for (int e = 0; e < 4; ++e) acc[nt][e] = 0.f;

        const int arow = lane >> 2;
        #pragma unroll 2
        for (int ks = 0; ks < 16; ++ks) {
            const int kk = ks * 16 + 2 * (lane & 3);
            uint32_t ah[4], al[4];
            {
                const int r0 = (m0 + arow) * AST;
                ah[0] = *(const uint32_t*)&Ah[r0 + kk];
                ah[1] = *(const uint32_t*)&Ah[r0 + 8 * AST + kk];
                ah[2] = *(const uint32_t*)&Ah[r0 + kk + 8];
                ah[3] = *(const uint32_t*)&Ah[r0 + 8 * AST + kk + 8];
                al[0] = *(const uint32_t*)&Al[r0 + kk];
                al[1] = *(const uint32_t*)&Al[r0 + 8 * AST + kk];
                al[2] = *(const uint32_t*)&Al[r0 + kk + 8];
                al[3] = *(const uint32_t*)&Al[r0 + 8 * AST + kk + 8];
            }
            #pragma unroll
            for (int nt = 0; nt < 3; ++nt) {
                const int nr = (n0 + nt * 8 + arow) * AST;
                const uint32_t bh0 = *(const uint32_t*)&Bh[nr + kk];
                const uint32_t bh1 = *(const uint32_t*)&Bh[nr + kk + 8];
                const uint32_t bl0 = *(const uint32_t*)&Bl[nr + kk];
                const uint32_t bl1 = *(const uint32_t*)&Bl[nr + kk + 8];
                MMA(acc[nt], ah, bh0, bh1);
                MMA(acc[nt], ah, bl0, bl1);
                MMA(acc[nt], al, bh0, bh1);
            }
        }

        // ---- epilogue: acc -> qt[oc][t] (transpose); 0.25 folded into q; ReLU on v ----
        #pragma unroll
        for (int nt = 0; nt < 3; ++nt) {
            const int row0 = m0 + arow, row1 = row0 + 8;
            const int col  = n0 + nt * 8 + 2 * (lane & 3);
            const int cls  = col % 48;                    // <16: q, <32: k, else v
            float c0 = acc[nt][0], c1 = acc[nt][1];
            float c2 = acc[nt][2], c3 = acc[nt][3];
            if (cls < 16)       { c0 *= 0.25f; c1 *= 0.25f; c2 *= 0.25f; c3 *= 0.25f; }
            else if (cls >= 32) {
                c0 = fmaxf(c0, 0.f); c1 = fmaxf(c1, 0.f);
                c2 = fmaxf(c2, 0.f); c3 = fmaxf(c3, 0.f);
            }
            if (row0 < 49) { qt[col * 57 + row0] = c0; qt[(col + 1) * 57 + row0] = c1; }
            if (row1 < 49) { qt[col * 57 + row1] = c2; qt[(col + 1) * 57 + row1] = c3; }
        }
        __syncthreads();     // all B-fragment reads + qt writes done

        // Prefetch next head-pair's weights; lands while attention below runs.
        if (hp < 7) stage_weights(sb, hp + 1, tid);

        // ---- S = q @ k^T (0.25 pre-folded), 16 warps: 2 heads x 8 j-groups ----
        {
            const int ah2 = warp >> 3, wq2 = warp & 7;
            const float* qb = qt + (ah2 * 48) * 57;
            const bool act1 = (lane + 32) < 49;
            float q0[16], q1[16];
            #pragma unroll
            for (int dd = 0; dd < 16; ++dd) {
                q0[dd] = qb[dd * 57 + lane];
                q1[dd] = act1 ? qb[dd * 57 + lane + 32] : 0.f;
            }
            #pragma unroll
            for (int jj = 0; jj < 7; ++jj) {
                const int j = wq2 * 7 + jj;
                if (j < 49) {
                    float s0 = 0.f, s1 = 0.f;
                    #pragma unroll
                    for (int dd = 0; dd < 16; ++dd) {
                        const float kv = qb[(16 + dd) * 57 + j];   // warp-uniform broadcast
                        s0 = fmaf(kv, q0[dd], s0);
                        s1 = fmaf(kv, q1[dd], s1);
                    }
                    st[(ah2 * 49 + j) * 50 + lane] = s0;
                    if (act1) st[(ah2 * 49 + j) * 50 + lane + 32] = s1;
                }
            }
        }
        __syncthreads();

        // ---- softmax over j per query i ----
        if (tid < 98) {
            const int ah2 = tid >= 49;
            const int i   = tid - ah2 * 49;
            float* col = st + ah2 * 49 * 50 + i;
            float m = -1e30f;
            #pragma unroll 7
            for (int j = 0; j < 49; ++j) m = fmaxf(m, col[j * 50]);
            float sum = 0.f;
            #pragma unroll 7
            for (int j = 0; j < 49; ++j) {
                const float e = __expf(col[j * 50] - m);
                col[j * 50] = e;
                sum += e;
            }
            const float rs = 1.f / sum;
            #pragma unroll 7
            for (int j = 0; j < 49; ++j) col[j * 50] *= rs;
        }
        __syncthreads();

        // ---- O = P @ V -> scatter to (B, C, H, W); 16 warps: 2 heads x 8 d-groups ----
        {
            const int ah2 = warp >> 3;
            const float* vb0 = qt + (ah2 * 48 + 32) * 57;
            const int head = hp * 2 + ah2;
            const bool act1 = (lane + 32) < 49;
            #pragma unroll
            for (int dd = 0; dd < 2; ++dd) {
                const int d = (warp & 7) * 2 + dd;
                const float* vb = vb0 + d * 57;
                float o0 = 0.f, o1 = 0.f;
                #pragma unroll 7
                for (int j = 0; j < 49; ++j) {
                    const float vv = vb[j];                         // warp-uniform broadcast
                    o0 = fmaf(vv, st[(ah2 * 49 + j) * 50 + lane], o0);
                    o1 = fmaf(vv, act1 ? st[(ah2 * 49 + j) * 50 + lane + 32] : 0.f, o1);
                }
                const size_t ch = (size_t)(head * 16 + d) * 3136;
                { const int i = lane, ti = i / 7, tj = i - (i / 7) * 7;
                  outb[ch + ti * 448 + tj * 8] = o0; }
                if (act1) {
                    const int i = lane + 32, ti = i / 7, tj = i - (i / 7) * 7;
                    outb[ch + ti * 448 + tj * 8] = o1;
                }
            }
        }
        // no trailing barrier: next hp's wait_group + __syncthreads orders qt/st reuse
    }
}

extern "C" void kernel_launch(void* const* d_in, const int* in_sizes, int n_in,
                              void* d_out, int out_size) {
    const float* x   = (const float*)d_in[0];
    const float* g   = (const float*)d_in[1];
    const float* be  = (const float*)d_in[2];
    const float* mu  = (const float*)d_in[3];
    const float* var = (const float*)d_in[4];
    const float* qkw = (const float*)d_in[5];
    const float* vw  = (const float*)d_in[6];
    float* out = (float*)d_out;

    wconv_kernel<<<768, 256>>>(qkw, vw);
    cudaFuncSetAttribute(wsa_kernel, cudaFuncAttributeMaxDynamicSharedMemorySize, SMEM_TOTAL);
    wsa_kernel<<<4096, 512, SMEM_TOTAL>>>(x, g, be, mu, var, out);
}

// round 11
// speedup vs baseline: 1.6052x; 1.0972x over previous
#include <cuda_runtime.h>
#include <cuda_bf16.h>
#include <cstdint>

// bf16 HMMA (legacy mma.sync — available on plain compute_103 PTX, unlike tcgen05)
#define MMA(c, a, b0, b1) \
    asm volatile("mma.sync.aligned.m16n8k16.row.col.f32.bf16.bf16.f32 " \
        "{%0,%1,%2,%3}, {%4,%5,%6,%7}, {%8,%9}, {%0,%1,%2,%3};" \
        : "+f"((c)[0]), "+f"((c)[1]), "+f"((c)[2]), "+f"((c)[3]) \
        : "r"((a)[0]), "r"((a)[1]), "r"((a)[2]), "r"((a)[3]), "r"(b0), "r"(b1))

__device__ __forceinline__ void cp16(uint32_t dst, const void* src) {
    asm volatile("cp.async.cg.shared.global [%0], [%1], 16;" :: "r"(dst), "l"(src));
}
__device__ __forceinline__ uint32_t smem_u32(const void* p) {
    uint32_t a;
    asm("{ .reg .u64 t; cvta.to.shared.u64 t, %1; cvt.u32.u64 %0, t; }" : "=r"(a) : "l"(p));
    return a;
}

// Pre-converted weights: [hp][96 rows][256 k] bf16 hi / lo. Row r of head-pair hp:
// hh=r>=48, oc=r-48*hh, head=2hp+hh; oc<16:q, <32:k, else v.
__device__ __nv_bfloat16 gWh[768 * 256];
__device__ __nv_bfloat16 gWl[768 * 256];

__global__ void wconv_kernel(const float* __restrict__ qkw, const float* __restrict__ vw) {
    const int g = blockIdx.x;          // 0..767
    const int k = threadIdx.x;         // 0..255
    const int hp = g / 96, r = g - hp * 96;
    const int hh = (r >= 48) ? 1 : 0;
    const int oc = r - 48 * hh;
    const int head = hp * 2 + hh;
    const float* src = (oc < 16) ? qkw + (head * 16 + oc) * 256
                     : (oc < 32) ? qkw + (256 + head * 16 + (oc - 16)) * 256
                                 : vw + (head * 16 + (oc - 32)) * 256;
    const float v = src[k];
    const __nv_bfloat16 h = __float2bfloat16(v);
    gWh[g * 256 + k] = h;
    gWl[g * 256 + k] = __float2bfloat16(v - __bfloat162float(h));
}

// Shapes: B=64, C=256, H=W=56, WS=7, HEADS=16, DH=16; 49 tokens/window (pad 64).
constexpr int AST = 264;                     // bf16 row stride: 528 B
constexpr int A_SZ = 64 * AST * 2;           // 33792 B
constexpr int B_SZ = 96 * AST * 2;           // 50688 B
constexpr int OFF_AH = 0;
constexpr int OFF_AL = OFF_AH + A_SZ;
constexpr int OFF_BH = OFF_AL + A_SZ;        // 67584
constexpr int OFF_BL = OFF_BH + B_SZ;        // 118272
constexpr int OFF_QT = OFF_BL + B_SZ;        // 168960: q|v [64 rows][60] f32 (rows: hh*32 + (q:0-15 | v:16-31))
constexpr int OFF_KT = OFF_QT + 64 * 60 * 4; // 184320: kt[2][64][20] f32  ([hh][t][d])
constexpr int OFF_ST = OFF_KT + 2 * 64 * 20 * 4; // 194560: st[ah][49][50] f32
constexpr int SMEM_TOTAL = OFF_ST + 2 * 49 * 50 * 4;   // 214160 B
constexpr int QTS = 60;                      // float4-aligned row stride
constexpr int KTS = 20;                      // float4-aligned; conflict-free epilogue stores

// Issue cp.async for head-pair hp's weights (hi+lo), one commit group.
__device__ __forceinline__ void stage_weights(uint32_t sb, int hp, int tid) {
    const __nv_bfloat16* srcH = gWh + hp * 96 * 256;
    const __nv_bfloat16* srcL = gWl + hp * 96 * 256;
    #pragma unroll
    for (int i = 0; i < 6; ++i) {
        const int idx = tid + i * 512;         // 96 rows x 32 chunks of 16 B
        const int r = idx >> 5, c8 = (idx & 31) * 8;
        cp16(sb + OFF_BH + (r * AST + c8) * 2, srcH + r * 256 + c8);
        cp16(sb + OFF_BL + (r * AST + c8) * 2, srcL + r * 256 + c8);
    }
    asm volatile("cp.async.commit_group;" ::: "memory");
}

__global__ __launch_bounds__(512, 1)
void wsa_kernel(const float* __restrict__ x,
                const float* __restrict__ bng, const float* __restrict__ bnb,
                const float* __restrict__ bnm, const float* __restrict__ bnv,
                float* __restrict__ out) {
    extern __shared__ char smem[];
    __nv_bfloat16* Ah = (__nv_bfloat16*)(smem + OFF_AH);
    __nv_bfloat16* Al = (__nv_bfloat16*)(smem + OFF_AL);
    __nv_bfloat16* Bh = (__nv_bfloat16*)(smem + OFF_BH);
    __nv_bfloat16* Bl = (__nv_bfloat16*)(smem + OFF_BL);
    float* qt = (float*)(smem + OFF_QT);     // q (0.25-scaled) and v(ReLU'd), [64][60]
    float* kt = (float*)(smem + OFF_KT);     // k, [hh][t][d] stride KTS
    float* st = (float*)(smem + OFF_ST);     // [ah][j][i] stride 50

    const uint32_t sb = smem_u32(smem);
    const int tid  = threadIdx.x;
    const int lane = tid & 31;
    const int warp = tid >> 5;
    const int wb   = blockIdx.x;
    const int b    = wb >> 6;
    const int n1   = (wb >> 3) & 7;
    const int n2   = wb & 7;

    // Kick off hp=0 weight staging immediately (overlaps the x gather below).
    stage_weights(sb, 0, tid);

    // ---- BN + stage A (tokens) as bf16 hi/lo, row-major [t][k]; 2 thread-halves split t ----
    {
        const int c  = tid & 255;
        const int th = tid >> 8;             // 0: t 0..24, 1: t 25..48
        const float inv = bng[c] / sqrtf(bnv[c] + 1e-6f);
        const float shf = bnb[c] - bnm[c] * inv;
        const float* xb = x + ((size_t)b * 256 + c) * 3136 + n1 * 56 + n2;
        const int tbeg = th ? 25 : 0, tend = th ? 49 : 25;
        for (int t = tbeg; t < tend; ++t) {
            const int ti = t / 7, tj = t - (t / 7) * 7;
            const float v = fmaf(xb[ti * 448 + tj * 8], inv, shf);
            const __nv_bfloat16 h = __float2bfloat16(v);
            Ah[t * AST + c] = h;
            Al[t * AST + c] = __float2bfloat16(v - __bfloat162float(h));
        }
        for (int i = tid; i < 15 * 128; i += 512) {        // zero pad rows 49..63
            const int row = 49 + (i >> 7), cc = (i & 127) * 2;
            *(uint32_t*)&Ah[row * AST + cc] = 0u;
            *(uint32_t*)&Al[row * AST + cc] = 0u;
        }
    }

    // 16 warps: m-tile = (warp&3)*16, n-tile = (warp>>2)*24
    const int m0 = (warp & 3) * 16, n0 = (warp >> 2) * 24;
    float* outb = out + (size_t)b * 256 * 3136 + n1 * 56 + n2;

    for (int hp = 0; hp < 8; ++hp) {           // head pair: heads 2hp, 2hp+1
        asm volatile("cp.async.wait_group 0;" ::: "memory");
        __syncthreads();

        // ---- projection: M64 x N96 x K256, split-bf16; 3 independent acc chains ----
        float ach[3][4], acm[3][4], acl[3][4];
        #pragma unroll
        for (int nt = 0; nt < 3; ++nt)
            #pragma unroll
            for (int e = 0; e < 4; ++e) { ach[nt][e] = 0.f; acm[nt][e] = 0.f; acl[nt][e] = 0.f; }

        const int arow = lane >> 2;
        #pragma unroll 2
        for (int ks = 0; ks < 16; ++ks) {
            const int kk = ks * 16 + 2 * (lane & 3);
            uint32_t ah[4], al[4];
            {
                const int r0 = (m0 + arow) * AST;
                ah[0] = *(const uint32_t*)&Ah[r0 + kk];
                ah[1] = *(const uint32_t*)&Ah[r0 + 8 * AST + kk];
                ah[2] = *(const uint32_t*)&Ah[r0 + kk + 8];
                ah[3] = *(const uint32_t*)&Ah[r0 + 8 * AST + kk + 8];
                al[0] = *(const uint32_t*)&Al[r0 + kk];
                al[1] = *(const uint32_t*)&Al[r0 + 8 * AST + kk];
                al[2] = *(const uint32_t*)&Al[r0 + kk + 8];
                al[3] = *(const uint32_t*)&Al[r0 + 8 * AST + kk + 8];
            }
            #pragma unroll
            for (int nt = 0; nt < 3; ++nt) {
                const int nr = (n0 + nt * 8 + arow) * AST;
                const uint32_t bh0 = *(const uint32_t*)&Bh[nr + kk];
                const uint32_t bh1 = *(const uint32_t*)&Bh[nr + kk + 8];
                const uint32_t bl0 = *(const uint32_t*)&Bl[nr + kk];
                const uint32_t bl1 = *(const uint32_t*)&Bl[nr + kk + 8];
                MMA(ach[nt], ah, bh0, bh1);
                MMA(acm[nt], ah, bl0, bl1);
                MMA(acl[nt], al, bh0, bh1);
            }
        }

        // ---- epilogue: merge chains; q*0.25 -> qt, k -> kt[t][d], v(ReLU) -> qt ----
        #pragma unroll
        for (int nt = 0; nt < 3; ++nt) {
            const int row0 = m0 + arow, row1 = row0 + 8;
            const int col  = n0 + nt * 8 + 2 * (lane & 3);   // even; pairs never straddle class
            const int hh   = col / 48;
            const int cls  = col % 48;                       // <16: q, <32: k, else v
            float c0 = ach[nt][0] + acm[nt][0] + acl[nt][0];
            float c1 = ach[nt][1] + acm[nt][1] + acl[nt][1];
            float c2 = ach[nt][2] + acm[nt][2] + acl[nt][2];
            float c3 = ach[nt][3] + acm[nt][3] + acl[nt][3];
            if (cls < 16) {
                c0 *= 0.25f; c1 *= 0.25f; c2 *= 0.25f; c3 *= 0.25f;
                float* r = qt + (hh * 32 + cls) * QTS;
                if (row0 < 49) { r[row0] = c0; r[QTS + row0] = c1; }
                if (row1 < 49) { r[row1] = c2; r[QTS + row1] = c3; }
            } else if (cls < 32) {
                float* kb = kt + hh * 64 * KTS + (cls - 16);
                if (row0 < 49) { kb[row0 * KTS] = c0; kb[row0 * KTS + 1] = c1; }
                if (row1 < 49) { kb[row1 * KTS] = c2; kb[row1 * KTS + 1] = c3; }
            } else {
                c0 = fmaxf(c0, 0.f); c1 = fmaxf(c1, 0.f);
                c2 = fmaxf(c2, 0.f); c3 = fmaxf(c3, 0.f);
                float* r = qt + (hh * 32 + 16 + (cls - 32)) * QTS;
                if (row0 < 49) { r[row0] = c0; r[QTS + row0] = c1; }
                if (row1 < 49) { r[row1] = c2; r[QTS + row1] = c3; }
            }
        }
        __syncthreads();     // all B-fragment reads + qt/kt writes done

        // Prefetch next head-pair's weights; lands while attention below runs.
        if (hp < 7) stage_weights(sb, hp + 1, tid);

        // ---- S = q @ k^T (0.25 pre-folded); k via float4 broadcasts ----
        {
            const int ah2 = warp >> 3, wq2 = warp & 7;
            const float* qb = qt + (ah2 * 32) * QTS;
            const float* kb = kt + ah2 * 64 * KTS;
            const bool act1 = (lane + 32) < 49;
            float q0[16], q1[16];
            #pragma unroll
            for (int dd = 0; dd < 16; ++dd) {
                q0[dd] = qb[dd * QTS + lane];
                q1[dd] = act1 ? qb[dd * QTS + lane + 32] : 0.f;
            }
            #pragma unroll
            for (int jj = 0; jj < 7; ++jj) {
                const int j = wq2 * 7 + jj;
                if (j < 49) {
                    float s0 = 0.f, s1 = 0.f;
                    #pragma unroll
                    for (int g = 0; g < 4; ++g) {
                        const float4 kv = *(const float4*)&kb[j * KTS + g * 4];  // broadcast
                        s0 = fmaf(kv.x, q0[g*4+0], s0); s1 = fmaf(kv.x, q1[g*4+0], s1);
                        s0 = fmaf(kv.y, q0[g*4+1], s0); s1 = fmaf(kv.y, q1[g*4+1], s1);
                        s0 = fmaf(kv.z, q0[g*4+2], s0); s1 = fmaf(kv.z, q1[g*4+2], s1);
                        s0 = fmaf(kv.w, q0[g*4+3], s0); s1 = fmaf(kv.w, q1[g*4+3], s1);
                    }
                    st[(ah2 * 49 + j) * 50 + lane] = s0;
                    if (act1) st[(ah2 * 49 + j) * 50 + lane + 32] = s1;
                }
            }
        }
        __syncthreads();

        // ---- softmax over j per query i ----
        if (tid < 98) {
            const int ah2 = tid >= 49;
            const int i   = tid - ah2 * 49;
            float* col = st + ah2 * 49 * 50 + i;
            float m = -1e30f;
            #pragma unroll 7
            for (int j = 0; j < 49; ++j) m = fmaxf(m, col[j * 50]);
            float sum = 0.f;
            #pragma unroll 7
            for (int j = 0; j < 49; ++j) {
                const float e = __expf(col[j * 50] - m);
                col[j * 50] = e;
                sum += e;
            }
            const float rs = 1.f / sum;
            #pragma unroll 7
            for (int j = 0; j < 49; ++j) col[j * 50] *= rs;
        }
        __syncthreads();

        // ---- O = P @ V; v float4, P rows hoisted across the two d ----
        {
            const int ah2 = warp >> 3;
            const int d0  = (warp & 7) * 2;
            const float* v0r = qt + (ah2 * 32 + 16 + d0) * QTS;
            const float* v1r = v0r + QTS;
            const float* pr  = st + (ah2 * 49) * 50;
            const int head = hp * 2 + ah2;
            const bool act1 = (lane + 32) < 49;
            float o00 = 0.f, o01 = 0.f, o10 = 0.f, o11 = 0.f;
            #pragma unroll 4
            for (int jc = 0; jc < 48; jc += 4) {
                const float4 v0 = *(const float4*)&v0r[jc];   // broadcast
                const float4 v1 = *(const float4*)&v1r[jc];
                #pragma unroll
                for (int e = 0; e < 4; ++e) {
                    const int j = jc + e;
                    const float p0 = pr[j * 50 + lane];
                    const float p1 = act1 ? pr[j * 50 + lane + 32] : 0.f;
                    const float ve0 = (e == 0) ? v0.x : (e == 1) ? v0.y : (e == 2) ? v0.z : v0.w;
                    const float ve1 = (e == 0) ? v1.x : (e == 1) ? v1.y : (e == 2) ? v1.z : v1.w;
                    o00 = fmaf(ve0, p0, o00); o01 = fmaf(ve0, p1, o01);
                    o10 = fmaf(ve1, p0, o10); o11 = fmaf(ve1, p1, o11);
                }
            }
            {   // j = 48 tail
                const float p0 = pr[48 * 50 + lane];
                const float p1 = act1 ? pr[48 * 50 + lane + 32] : 0.f;
                o00 = fmaf(v0r[48], p0, o00); o01 = fmaf(v0r[48], p1, o01);
                o10 = fmaf(v1r[48], p0, o10); o11 = fmaf(v1r[48], p1, o11);
            }
            const int i0 = lane, ti0 = i0 / 7, tj0 = i0 - (i0 / 7) * 7;
            const size_t ch0 = (size_t)(head * 16 + d0) * 3136;
            const size_t ch1 = ch0 + 3136;
            outb[ch0 + ti0 * 448 + tj0 * 8] = o00;
            outb[ch1 + ti0 * 448 + tj0 * 8] = o10;
            if (act1) {
                const int i1 = lane + 32, ti1 = i1 / 7, tj1 = i1 - (i1 / 7) * 7;
                outb[ch0 + ti1 * 448 + tj1 * 8] = o01;
                outb[ch1 + ti1 * 448 + tj1 * 8] = o11;
            }
        }
        // no trailing barrier: next hp's wait_group + __syncthreads orders qt/kt/st reuse
    }
}

extern "C" void kernel_launch(void* const* d_in, const int* in_sizes, int n_in,
                              void* d_out, int out_size) {
    const float* x   = (const float*)d_in[0];
    const float* g   = (const float*)d_in[1];
    const float* be  = (const float*)d_in[2];
    const float* mu  = (const float*)d_in[3];
    const float* var = (const float*)d_in[4];
    const float* qkw = (const float*)d_in[5];
    const float* vw  = (const float*)d_in[6];
    float* out = (float*)d_out;

    wconv_kernel<<<768, 256>>>(qkw, vw);
    cudaFuncSetAttribute(wsa_kernel, cudaFuncAttributeMaxDynamicSharedMemorySize, SMEM_TOTAL);
    wsa_kernel<<<4096, 512, SMEM_TOTAL>>>(x, g, be, mu, var, out);
}